// round 1
// baseline (speedup 1.0000x reference)
#include <cuda_runtime.h>

#define BB 4
#define SEQ 2048
#define EMB 1024
#define NH 16
#define HD 64
#define MT (BB * SEQ)  // 8192 tokens

// Scratch (allocation-free rule: device globals)
__device__ float g_q[BB * NH * SEQ * HD];   // [b][h][s][d]
__device__ float g_k[BB * NH * SEQ * HD];
__device__ float g_v[BB * NH * SEQ * HD];
__device__ float g_ao[MT * EMB];            // attention out, [b][s][h*64+d] == [m][e]

// ---------------------------------------------------------------------------
// GEMM1: qkv[m][n] = sum_k query[m][k] * Wqkv[n][k] + bqkv[n]
// scatter into g_q/g_k/g_v laid out [b][h][s][d]
// BM=BN=64, BK=16, 256 threads, 4x4 per-thread tile
// ---------------------------------------------------------------------------
__global__ __launch_bounds__(256) void qkv_gemm_kernel(
    const float* __restrict__ A, const float* __restrict__ W,
    const float* __restrict__ bias) {
  __shared__ float As[16][68];
  __shared__ float Bs[16][68];
  const int tid = threadIdx.x;
  const int m0 = blockIdx.y * 64;
  const int n0 = blockIdx.x * 64;
  const int lr = tid >> 2;            // 0..63 row in tile
  const int lc = (tid & 3) * 4;       // 0,4,8,12 k-offset
  const int ty = (tid >> 4) * 4;      // 0..60 m-offset
  const int tx = (tid & 15) * 4;      // 0..60 n-offset
  float acc[4][4] = {};

  const float* Ap = A + (m0 + lr) * EMB + lc;
  const float* Wp = W + (n0 + lr) * EMB + lc;

  for (int k0 = 0; k0 < EMB; k0 += 16) {
    float4 a4 = *(const float4*)(Ap + k0);
    float4 b4 = *(const float4*)(Wp + k0);
    As[lc + 0][lr] = a4.x; As[lc + 1][lr] = a4.y;
    As[lc + 2][lr] = a4.z; As[lc + 3][lr] = a4.w;
    Bs[lc + 0][lr] = b4.x; Bs[lc + 1][lr] = b4.y;
    Bs[lc + 2][lr] = b4.z; Bs[lc + 3][lr] = b4.w;
    __syncthreads();
#pragma unroll
    for (int kk = 0; kk < 16; kk++) {
      float4 av = *(const float4*)&As[kk][ty];
      float4 bv = *(const float4*)&Bs[kk][tx];
      float a_[4] = {av.x, av.y, av.z, av.w};
      float b_[4] = {bv.x, bv.y, bv.z, bv.w};
#pragma unroll
      for (int i = 0; i < 4; i++)
#pragma unroll
        for (int j = 0; j < 4; j++)
          acc[i][j] = fmaf(a_[i], b_[j], acc[i][j]);
    }
    __syncthreads();
  }

  // epilogue: bias + scatter to q/k/v
#pragma unroll
  for (int i = 0; i < 4; i++) {
    const int m = m0 + ty + i;
    const int b = m >> 11;          // m / SEQ
    const int s = m & 2047;         // m % SEQ
#pragma unroll
    for (int j = 0; j < 4; j++) {
      const int n = n0 + tx + j;
      const float val = acc[i][j] + bias[n];
      const int which = n >> 10;    // 0=q 1=k 2=v
      const int rem = n & 1023;
      const int h = rem >> 6;
      const int d = rem & 63;
      float* dst = (which == 0) ? g_q : (which == 1) ? g_k : g_v;
      dst[(((b << 4) + h) * SEQ + s) * HD + d] = val;
    }
  }
}

// ---------------------------------------------------------------------------
// GEMM2: out[m][n] = sum_k g_ao[m][k] * Wout[n][k] + bout[n]
// ---------------------------------------------------------------------------
__global__ __launch_bounds__(256) void out_gemm_kernel(
    const float* __restrict__ W, const float* __restrict__ bias,
    float* __restrict__ out) {
  __shared__ float As[16][68];
  __shared__ float Bs[16][68];
  const int tid = threadIdx.x;
  const int m0 = blockIdx.y * 64;
  const int n0 = blockIdx.x * 64;
  const int lr = tid >> 2;
  const int lc = (tid & 3) * 4;
  const int ty = (tid >> 4) * 4;
  const int tx = (tid & 15) * 4;
  float acc[4][4] = {};

  const float* Ap = g_ao + (m0 + lr) * EMB + lc;
  const float* Wp = W + (n0 + lr) * EMB + lc;

  for (int k0 = 0; k0 < EMB; k0 += 16) {
    float4 a4 = *(const float4*)(Ap + k0);
    float4 b4 = *(const float4*)(Wp + k0);
    As[lc + 0][lr] = a4.x; As[lc + 1][lr] = a4.y;
    As[lc + 2][lr] = a4.z; As[lc + 3][lr] = a4.w;
    Bs[lc + 0][lr] = b4.x; Bs[lc + 1][lr] = b4.y;
    Bs[lc + 2][lr] = b4.z; Bs[lc + 3][lr] = b4.w;
    __syncthreads();
#pragma unroll
    for (int kk = 0; kk < 16; kk++) {
      float4 av = *(const float4*)&As[kk][ty];
      float4 bv = *(const float4*)&Bs[kk][tx];
      float a_[4] = {av.x, av.y, av.z, av.w};
      float b_[4] = {bv.x, bv.y, bv.z, bv.w};
#pragma unroll
      for (int i = 0; i < 4; i++)
#pragma unroll
        for (int j = 0; j < 4; j++)
          acc[i][j] = fmaf(a_[i], b_[j], acc[i][j]);
    }
    __syncthreads();
  }

#pragma unroll
  for (int i = 0; i < 4; i++) {
    const int m = m0 + ty + i;
#pragma unroll
    for (int j = 0; j < 4; j++) {
      const int n = n0 + tx + j;
      out[m * EMB + n] = acc[i][j] + bias[n];
    }
  }
}

// ---------------------------------------------------------------------------
// Flash attention: one block per (b*h, q-tile of 64). KV tiles of 32.
// scores scaled by 1/sqrt(EMB) = 1/32 (ref scales by embed_dim, not head_dim)
// ---------------------------------------------------------------------------
__global__ __launch_bounds__(256) void flash_attn_kernel() {
  __shared__ float Qs[64][68];   // [d][q] transposed
  __shared__ float Ks[64][36];   // [d][k] transposed
  __shared__ float Vs[32][64];   // [k][d]
  __shared__ float Ps[64][36];   // scores -> probs, [q][k]
  __shared__ float m_s[64], l_s[64], rsc[64];

  const int tid = threadIdx.x;
  const int bh = blockIdx.x;          // 0..63
  const int q0 = blockIdx.y * 64;     // 0..2047
  const int b = bh >> 4, h = bh & 15;

  const float* Qg = g_q + (bh * SEQ + q0) * HD;
  const float* Kg = g_k + bh * SEQ * HD;
  const float* Vg = g_v + bh * SEQ * HD;

  // load Q tile transposed (once)
#pragma unroll
  for (int it = 0; it < 4; it++) {
    const int idx = it * 256 + tid;
    const int r = idx >> 4;
    const int c = (idx & 15) * 4;
    float4 v = *(const float4*)(Qg + r * HD + c);
    Qs[c + 0][r] = v.x; Qs[c + 1][r] = v.y;
    Qs[c + 2][r] = v.z; Qs[c + 3][r] = v.w;
  }
  if (tid < 64) { m_s[tid] = -1e30f; l_s[tid] = 0.f; }

  const int ty = (tid >> 4) * 4;      // q offset (score + PV)
  const int txa = (tid & 15) * 2;     // k offset (scores)
  const int txc = (tid & 15) * 4;     // d offset (PV)
  const int rrow = tid >> 2;          // softmax row
  const int part = tid & 3;
  const int kb = part * 8;

  float acc[4][4] = {};

  for (int j0 = 0; j0 < SEQ; j0 += 32) {
    __syncthreads();  // protect K/V/Ps from previous iter readers (covers Q load 1st iter)

    // load K transposed + V
#pragma unroll
    for (int it = 0; it < 2; it++) {
      const int idx = it * 256 + tid;
      const int rr = idx >> 4;
      const int c = (idx & 15) * 4;
      float4 kv = *(const float4*)(Kg + (j0 + rr) * HD + c);
      Ks[c + 0][rr] = kv.x; Ks[c + 1][rr] = kv.y;
      Ks[c + 2][rr] = kv.z; Ks[c + 3][rr] = kv.w;
      float4 vv = *(const float4*)(Vg + (j0 + rr) * HD + c);
      *(float4*)&Vs[rr][c] = vv;
    }
    __syncthreads();

    // scores: S[64][32] = Q @ K^T
    float sacc[4][2] = {};
#pragma unroll 16
    for (int d = 0; d < 64; d++) {
      float4 q4 = *(const float4*)&Qs[d][ty];
      float2 k2 = *(const float2*)&Ks[d][txa];
      sacc[0][0] = fmaf(q4.x, k2.x, sacc[0][0]);
      sacc[0][1] = fmaf(q4.x, k2.y, sacc[0][1]);
      sacc[1][0] = fmaf(q4.y, k2.x, sacc[1][0]);
      sacc[1][1] = fmaf(q4.y, k2.y, sacc[1][1]);
      sacc[2][0] = fmaf(q4.z, k2.x, sacc[2][0]);
      sacc[2][1] = fmaf(q4.z, k2.y, sacc[2][1]);
      sacc[3][0] = fmaf(q4.w, k2.x, sacc[3][0]);
      sacc[3][1] = fmaf(q4.w, k2.y, sacc[3][1]);
    }
#pragma unroll
    for (int i = 0; i < 4; i++) {
      Ps[ty + i][txa + 0] = sacc[i][0] * 0.03125f;
      Ps[ty + i][txa + 1] = sacc[i][1] * 0.03125f;
    }
    __syncthreads();

    // online softmax: 4 threads per row
    {
      const float old_m = m_s[rrow];
      const float old_l = l_s[rrow];
      float mx = -1e30f;
#pragma unroll
      for (int u = 0; u < 8; u++) mx = fmaxf(mx, Ps[rrow][kb + u]);
      mx = fmaxf(mx, __shfl_xor_sync(0xffffffffu, mx, 1));
      mx = fmaxf(mx, __shfl_xor_sync(0xffffffffu, mx, 2));
      const float m_new = fmaxf(old_m, mx);
      float lsum = 0.f;
#pragma unroll
      for (int u = 0; u < 8; u++) {
        const float p = __expf(Ps[rrow][kb + u] - m_new);
        Ps[rrow][kb + u] = p;
        lsum += p;
      }
      lsum += __shfl_xor_sync(0xffffffffu, lsum, 1);
      lsum += __shfl_xor_sync(0xffffffffu, lsum, 2);
      if (part == 0) {
        const float corr = __expf(old_m - m_new);
        m_s[rrow] = m_new;
        l_s[rrow] = old_l * corr + lsum;
        rsc[rrow] = corr;
      }
    }
    __syncthreads();

    // O = O*corr + P @ V
    {
      const float rs0 = rsc[ty + 0], rs1 = rsc[ty + 1];
      const float rs2 = rsc[ty + 2], rs3 = rsc[ty + 3];
#pragma unroll
      for (int j = 0; j < 4; j++) {
        acc[0][j] *= rs0; acc[1][j] *= rs1;
        acc[2][j] *= rs2; acc[3][j] *= rs3;
      }
#pragma unroll 16
      for (int kk = 0; kk < 32; kk++) {
        const float p0 = Ps[ty + 0][kk];
        const float p1 = Ps[ty + 1][kk];
        const float p2 = Ps[ty + 2][kk];
        const float p3 = Ps[ty + 3][kk];
        float4 v4 = *(const float4*)&Vs[kk][txc];
        acc[0][0] = fmaf(p0, v4.x, acc[0][0]);
        acc[0][1] = fmaf(p0, v4.y, acc[0][1]);
        acc[0][2] = fmaf(p0, v4.z, acc[0][2]);
        acc[0][3] = fmaf(p0, v4.w, acc[0][3]);
        acc[1][0] = fmaf(p1, v4.x, acc[1][0]);
        acc[1][1] = fmaf(p1, v4.y, acc[1][1]);
        acc[1][2] = fmaf(p1, v4.z, acc[1][2]);
        acc[1][3] = fmaf(p1, v4.w, acc[1][3]);
        acc[2][0] = fmaf(p2, v4.x, acc[2][0]);
        acc[2][1] = fmaf(p2, v4.y, acc[2][1]);
        acc[2][2] = fmaf(p2, v4.z, acc[2][2]);
        acc[2][3] = fmaf(p2, v4.w, acc[2][3]);
        acc[3][0] = fmaf(p3, v4.x, acc[3][0]);
        acc[3][1] = fmaf(p3, v4.y, acc[3][1]);
        acc[3][2] = fmaf(p3, v4.z, acc[3][2]);
        acc[3][3] = fmaf(p3, v4.w, acc[3][3]);
      }
    }
  }

  // finalize: divide by l, store to g_ao [b][s][h*64+d]
#pragma unroll
  for (int i = 0; i < 4; i++) {
    const float linv = 1.f / l_s[ty + i];
    const int s = q0 + ty + i;
    float* op = g_ao + (b * SEQ + s) * EMB + h * HD + txc;
#pragma unroll
    for (int j = 0; j < 4; j++) op[j] = acc[i][j] * linv;
  }
}

// ---------------------------------------------------------------------------
extern "C" void kernel_launch(void* const* d_in, const int* in_sizes, int n_in,
                              void* d_out, int out_size) {
  (void)in_sizes; (void)n_in; (void)out_size;
  const float* query = (const float*)d_in[0];
  // d_in[1]=key, d_in[2]=value: ignored by the reference module
  const float* Wqkv = (const float*)d_in[3];
  const float* bqkv = (const float*)d_in[4];
  const float* Wout = (const float*)d_in[5];
  const float* bout = (const float*)d_in[6];
  float* out = (float*)d_out;

  dim3 g1(48, 128);   // 3072/64 x 8192/64
  qkv_gemm_kernel<<<g1, 256>>>(query, Wqkv, bqkv);

  dim3 g2(64, 32);    // (b*h) x (S/64)
  flash_attn_kernel<<<g2, 256>>>();

  dim3 g3(16, 128);   // 1024/64 x 8192/64
  out_gemm_kernel<<<g3, 256>>>(Wout, bout, out);
}

// round 3
// speedup vs baseline: 1.1619x; 1.1619x over previous
#include <cuda_runtime.h>
#include <cstdint>

#define BB 4
#define SEQ 2048
#define EMB 1024
#define NH 16
#define HD 64
#define MT (BB * SEQ)  // 8192 tokens

// Scratch (allocation-free rule: device globals)
__device__ float g_q[BB * NH * SEQ * HD];   // [b][h][s][d]
__device__ float g_k[BB * NH * SEQ * HD];
__device__ float g_v[BB * NH * SEQ * HD];
__device__ float g_ao[MT * EMB];            // attention out, [b][s][h*64+d] == [m][e]

// ---------------------------------------------------------------------------
// tf32 helpers (baseline PTX, works at .target sm_100)
// ---------------------------------------------------------------------------
__device__ __forceinline__ uint32_t f2tf32(float x) {
  uint32_t r;
  asm("cvt.rna.tf32.f32 %0, %1;" : "=r"(r) : "f"(x));
  return r;
}

__device__ __forceinline__ void split1(float v, uint32_t& h, uint32_t& l) {
  h = f2tf32(v);
  l = f2tf32(v - __uint_as_float(h));
}

__device__ __forceinline__ void mma_tf32(float* c, const uint32_t* a,
                                         const uint32_t* b) {
  asm volatile(
      "mma.sync.aligned.m16n8k8.row.col.f32.tf32.tf32.f32 "
      "{%0,%1,%2,%3}, {%4,%5,%6,%7}, {%8,%9}, {%0,%1,%2,%3};"
      : "+f"(c[0]), "+f"(c[1]), "+f"(c[2]), "+f"(c[3])
      : "r"(a[0]), "r"(a[1]), "r"(a[2]), "r"(a[3]), "r"(b[0]), "r"(b[1]));
}

// ---------------------------------------------------------------------------
// tf32 3x-split GEMM via mma.sync: D[m][n] = sum_k A[m][k]*B[n][k] + bias[n]
// CTA 128x128, BK=16, 256 threads (8 warps, each 64x32 out).
// Split done once per element at STS time (Ahi/Alo/Bhi/Blo smem tiles).
// MODE 0: A=query, scatter into g_q/g_k/g_v. MODE 1: A=g_ao, write out.
// ---------------------------------------------------------------------------
#define SPAD 20  // row stride in words for 16-col tile (conflict-free frags)

template <int MODE>
__global__ __launch_bounds__(256) void gemm_mma_kernel(
    const float* __restrict__ A, const float* __restrict__ B,
    const float* __restrict__ bias, float* __restrict__ out) {
  __shared__ uint32_t s_ahi[128 * SPAD];
  __shared__ uint32_t s_alo[128 * SPAD];
  __shared__ uint32_t s_bhi[128 * SPAD];
  __shared__ uint32_t s_blo[128 * SPAD];

  const int tid = threadIdx.x;
  const int lane = tid & 31;
  const int wid = tid >> 5;
  const int warp_m = wid & 1;        // 2 warps over M
  const int warp_n = wid >> 1;       // 4 warps over N
  const int m0 = blockIdx.y * 128;
  const int n0 = blockIdx.x * 128;

  const float* Asrc = (MODE == 0) ? A : g_ao;

  // global load mapping: idx in [0,512): row=idx>>2 (0..127), col=(idx&3)*4
  const int ldr = tid >> 2;          // rows 0..63 (+64 for second half)
  const int ldc = (tid & 3) * 4;     // 0,4,8,12

  const float* Ap0 = Asrc + (size_t)(m0 + ldr) * EMB + ldc;
  const float* Ap1 = Asrc + (size_t)(m0 + 64 + ldr) * EMB + ldc;
  const float* Bp0 = B + (size_t)(n0 + ldr) * EMB + ldc;
  const float* Bp1 = B + (size_t)(n0 + 64 + ldr) * EMB + ldc;

  float acc[4][4][4] = {};  // [mt][nt][reg]

  float4 pa0, pa1, pb0, pb1;
  pa0 = *(const float4*)(Ap0);
  pa1 = *(const float4*)(Ap1);
  pb0 = *(const float4*)(Bp0);
  pb1 = *(const float4*)(Bp1);

  const int s0 = ldr * SPAD + ldc;
  const int s1 = (ldr + 64) * SPAD + ldc;

  for (int c = 0; c < EMB / 16; ++c) {
    if (c > 0) __syncthreads();  // previous compute readers done

    // split + store to smem
    {
      uint4 h, l;
      split1(pa0.x, h.x, l.x); split1(pa0.y, h.y, l.y);
      split1(pa0.z, h.z, l.z); split1(pa0.w, h.w, l.w);
      *(uint4*)&s_ahi[s0] = h; *(uint4*)&s_alo[s0] = l;
      split1(pa1.x, h.x, l.x); split1(pa1.y, h.y, l.y);
      split1(pa1.z, h.z, l.z); split1(pa1.w, h.w, l.w);
      *(uint4*)&s_ahi[s1] = h; *(uint4*)&s_alo[s1] = l;
      split1(pb0.x, h.x, l.x); split1(pb0.y, h.y, l.y);
      split1(pb0.z, h.z, l.z); split1(pb0.w, h.w, l.w);
      *(uint4*)&s_bhi[s0] = h; *(uint4*)&s_blo[s0] = l;
      split1(pb1.x, h.x, l.x); split1(pb1.y, h.y, l.y);
      split1(pb1.z, h.z, l.z); split1(pb1.w, h.w, l.w);
      *(uint4*)&s_bhi[s1] = h; *(uint4*)&s_blo[s1] = l;
    }
    __syncthreads();

    // prefetch next chunk
    if (c + 1 < EMB / 16) {
      const int off = (c + 1) * 16;
      pa0 = *(const float4*)(Ap0 + off);
      pa1 = *(const float4*)(Ap1 + off);
      pb0 = *(const float4*)(Bp0 + off);
      pb1 = *(const float4*)(Bp1 + off);
    }

    // compute: two k8 sub-chunks
#pragma unroll
    for (int kc = 0; kc < 2; ++kc) {
      const int kb = kc * 8 + (lane & 3);
      uint32_t ah[4][4], al[4][4];
#pragma unroll
      for (int mt = 0; mt < 4; ++mt) {
        const int r = warp_m * 64 + mt * 16 + (lane >> 2);
        const int i0 = r * SPAD + kb;
        const int i1 = (r + 8) * SPAD + kb;
        ah[mt][0] = s_ahi[i0];     ah[mt][1] = s_ahi[i1];
        ah[mt][2] = s_ahi[i0 + 4]; ah[mt][3] = s_ahi[i1 + 4];
        al[mt][0] = s_alo[i0];     al[mt][1] = s_alo[i1];
        al[mt][2] = s_alo[i0 + 4]; al[mt][3] = s_alo[i1 + 4];
      }
      uint32_t bh[4][2], bl[4][2];
#pragma unroll
      for (int nt = 0; nt < 4; ++nt) {
        const int n = warp_n * 32 + nt * 8 + (lane >> 2);
        const int i0 = n * SPAD + kb;
        bh[nt][0] = s_bhi[i0]; bh[nt][1] = s_bhi[i0 + 4];
        bl[nt][0] = s_blo[i0]; bl[nt][1] = s_blo[i0 + 4];
      }
#pragma unroll
      for (int mt = 0; mt < 4; ++mt)
#pragma unroll
        for (int nt = 0; nt < 4; ++nt) {
          mma_tf32(acc[mt][nt], ah[mt], bh[nt]);
          mma_tf32(acc[mt][nt], ah[mt], bl[nt]);
          mma_tf32(acc[mt][nt], al[mt], bh[nt]);
        }
    }
  }

  // epilogue: bias + store (float2 per c-pair)
#pragma unroll
  for (int mt = 0; mt < 4; ++mt) {
#pragma unroll
    for (int nt = 0; nt < 4; ++nt) {
      const int r = m0 + warp_m * 64 + mt * 16 + (lane >> 2);
      const int n = n0 + warp_n * 32 + nt * 8 + (lane & 3) * 2;
      const float b0 = bias[n], b1 = bias[n + 1];
      float2 v0 = {acc[mt][nt][0] + b0, acc[mt][nt][1] + b1};
      float2 v1 = {acc[mt][nt][2] + b0, acc[mt][nt][3] + b1};
      if (MODE == 0) {
        const int which = n >> 10;  // tile never straddles q/k/v
        float* dstv = (which == 0) ? g_q : (which == 1) ? g_k : g_v;
        const int rem = n & 1023;
        const int h = rem >> 6;
        const int d = rem & 63;
        const int b_ = r >> 11, s_ = r & 2047;
        float* base = dstv + (size_t)(((b_ << 4) + h) * SEQ) * HD + d;
        *(float2*)(base + (size_t)s_ * HD) = v0;
        *(float2*)(base + (size_t)(s_ + 8) * HD) = v1;
      } else {
        *(float2*)(out + (size_t)r * EMB + n) = v0;
        *(float2*)(out + (size_t)(r + 8) * EMB + n) = v1;
      }
    }
  }
}

// ---------------------------------------------------------------------------
// Flash attention (SIMT, unchanged from R1): one block per (b*h, q-tile 64).
// scores scaled by 1/sqrt(EMB) = 1/32
// ---------------------------------------------------------------------------
__global__ __launch_bounds__(256) void flash_attn_kernel() {
  __shared__ float Qs[64][68];   // [d][q] transposed
  __shared__ float Ks[64][36];   // [d][k] transposed
  __shared__ float Vs[32][64];   // [k][d]
  __shared__ float Ps[64][36];   // scores -> probs, [q][k]
  __shared__ float m_s[64], l_s[64], rsc[64];

  const int tid = threadIdx.x;
  const int bh = blockIdx.x;          // 0..63
  const int q0 = blockIdx.y * 64;     // 0..2047
  const int b = bh >> 4, h = bh & 15;

  const float* Qg = g_q + (bh * SEQ + q0) * HD;
  const float* Kg = g_k + bh * SEQ * HD;
  const float* Vg = g_v + bh * SEQ * HD;

#pragma unroll
  for (int it = 0; it < 4; it++) {
    const int idx = it * 256 + tid;
    const int r = idx >> 4;
    const int c = (idx & 15) * 4;
    float4 v = *(const float4*)(Qg + r * HD + c);
    Qs[c + 0][r] = v.x; Qs[c + 1][r] = v.y;
    Qs[c + 2][r] = v.z; Qs[c + 3][r] = v.w;
  }
  if (tid < 64) { m_s[tid] = -1e30f; l_s[tid] = 0.f; }

  const int ty = (tid >> 4) * 4;      // q offset (score + PV)
  const int txa = (tid & 15) * 2;     // k offset (scores)
  const int txc = (tid & 15) * 4;     // d offset (PV)
  const int rrow = tid >> 2;          // softmax row
  const int part = tid & 3;
  const int kb = part * 8;

  float acc[4][4] = {};

  for (int j0 = 0; j0 < SEQ; j0 += 32) {
    __syncthreads();

#pragma unroll
    for (int it = 0; it < 2; it++) {
      const int idx = it * 256 + tid;
      const int rr = idx >> 4;
      const int c = (idx & 15) * 4;
      float4 kv = *(const float4*)(Kg + (j0 + rr) * HD + c);
      Ks[c + 0][rr] = kv.x; Ks[c + 1][rr] = kv.y;
      Ks[c + 2][rr] = kv.z; Ks[c + 3][rr] = kv.w;
      float4 vv = *(const float4*)(Vg + (j0 + rr) * HD + c);
      *(float4*)&Vs[rr][c] = vv;
    }
    __syncthreads();

    float sacc[4][2] = {};
#pragma unroll 16
    for (int d = 0; d < 64; d++) {
      float4 q4 = *(const float4*)&Qs[d][ty];
      float2 k2 = *(const float2*)&Ks[d][txa];
      sacc[0][0] = fmaf(q4.x, k2.x, sacc[0][0]);
      sacc[0][1] = fmaf(q4.x, k2.y, sacc[0][1]);
      sacc[1][0] = fmaf(q4.y, k2.x, sacc[1][0]);
      sacc[1][1] = fmaf(q4.y, k2.y, sacc[1][1]);
      sacc[2][0] = fmaf(q4.z, k2.x, sacc[2][0]);
      sacc[2][1] = fmaf(q4.z, k2.y, sacc[2][1]);
      sacc[3][0] = fmaf(q4.w, k2.x, sacc[3][0]);
      sacc[3][1] = fmaf(q4.w, k2.y, sacc[3][1]);
    }
#pragma unroll
    for (int i = 0; i < 4; i++) {
      Ps[ty + i][txa + 0] = sacc[i][0] * 0.03125f;
      Ps[ty + i][txa + 1] = sacc[i][1] * 0.03125f;
    }
    __syncthreads();

    {
      const float old_m = m_s[rrow];
      const float old_l = l_s[rrow];
      float mx = -1e30f;
#pragma unroll
      for (int u = 0; u < 8; u++) mx = fmaxf(mx, Ps[rrow][kb + u]);
      mx = fmaxf(mx, __shfl_xor_sync(0xffffffffu, mx, 1));
      mx = fmaxf(mx, __shfl_xor_sync(0xffffffffu, mx, 2));
      const float m_new = fmaxf(old_m, mx);
      float lsum = 0.f;
#pragma unroll
      for (int u = 0; u < 8; u++) {
        const float p = __expf(Ps[rrow][kb + u] - m_new);
        Ps[rrow][kb + u] = p;
        lsum += p;
      }
      lsum += __shfl_xor_sync(0xffffffffu, lsum, 1);
      lsum += __shfl_xor_sync(0xffffffffu, lsum, 2);
      if (part == 0) {
        const float corr = __expf(old_m - m_new);
        m_s[rrow] = m_new;
        l_s[rrow] = old_l * corr + lsum;
        rsc[rrow] = corr;
      }
    }
    __syncthreads();

    {
      const float rs0 = rsc[ty + 0], rs1 = rsc[ty + 1];
      const float rs2 = rsc[ty + 2], rs3 = rsc[ty + 3];
#pragma unroll
      for (int j = 0; j < 4; j++) {
        acc[0][j] *= rs0; acc[1][j] *= rs1;
        acc[2][j] *= rs2; acc[3][j] *= rs3;
      }
#pragma unroll 16
      for (int kk = 0; kk < 32; kk++) {
        const float p0 = Ps[ty + 0][kk];
        const float p1 = Ps[ty + 1][kk];
        const float p2 = Ps[ty + 2][kk];
        const float p3 = Ps[ty + 3][kk];
        float4 v4 = *(const float4*)&Vs[kk][txc];
        acc[0][0] = fmaf(p0, v4.x, acc[0][0]);
        acc[0][1] = fmaf(p0, v4.y, acc[0][1]);
        acc[0][2] = fmaf(p0, v4.z, acc[0][2]);
        acc[0][3] = fmaf(p0, v4.w, acc[0][3]);
        acc[1][0] = fmaf(p1, v4.x, acc[1][0]);
        acc[1][1] = fmaf(p1, v4.y, acc[1][1]);
        acc[1][2] = fmaf(p1, v4.z, acc[1][2]);
        acc[1][3] = fmaf(p1, v4.w, acc[1][3]);
        acc[2][0] = fmaf(p2, v4.x, acc[2][0]);
        acc[2][1] = fmaf(p2, v4.y, acc[2][1]);
        acc[2][2] = fmaf(p2, v4.z, acc[2][2]);
        acc[2][3] = fmaf(p2, v4.w, acc[2][3]);
        acc[3][0] = fmaf(p3, v4.x, acc[3][0]);
        acc[3][1] = fmaf(p3, v4.y, acc[3][1]);
        acc[3][2] = fmaf(p3, v4.z, acc[3][2]);
        acc[3][3] = fmaf(p3, v4.w, acc[3][3]);
      }
    }
  }

#pragma unroll
  for (int i = 0; i < 4; i++) {
    const float linv = 1.f / l_s[ty + i];
    const int s = q0 + ty + i;
    float* op = g_ao + (b * SEQ + s) * EMB + h * HD + txc;
#pragma unroll
    for (int j = 0; j < 4; j++) op[j] = acc[i][j] * linv;
  }
}

// ---------------------------------------------------------------------------
extern "C" void kernel_launch(void* const* d_in, const int* in_sizes, int n_in,
                              void* d_out, int out_size) {
  (void)in_sizes; (void)n_in; (void)out_size;
  const float* query = (const float*)d_in[0];
  // d_in[1]=key, d_in[2]=value: ignored by the reference module
  const float* Wqkv = (const float*)d_in[3];
  const float* bqkv = (const float*)d_in[4];
  const float* Wout = (const float*)d_in[5];
  const float* bout = (const float*)d_in[6];
  float* out = (float*)d_out;

  dim3 g1(24, 64);   // 3072/128 x 8192/128
  gemm_mma_kernel<0><<<g1, 256>>>(query, Wqkv, bqkv, nullptr);

  dim3 g2(64, 32);   // (b*h) x (S/64)
  flash_attn_kernel<<<g2, 256>>>();

  dim3 g3(8, 64);    // 1024/128 x 8192/128
  gemm_mma_kernel<1><<<g3, 256>>>(nullptr, Wout, bout, out);
}